// round 11
// baseline (speedup 1.0000x reference)
#include <cuda_runtime.h>

typedef unsigned long long u64;

#define TPB 128
#define PXT 4                    // pixels per thread (2 f32x2 pairs)
#define PXB (TPB * PXT)          // 512 pixels per block

// constant layout (u64 duplicated pairs):
// [0..87]    W0 (8x11, z-scale folded)
// [88..95]   b0
// [96..159]  Wm * 1      (layer 0)
// [160..223] Wm * 0.5    (layer 1)
// [224..287] Wm * 0.25   (layer 2)
// [288..295] bm
// [296..319] Wo / 16     (1/8 residual unscale + 0.5 sigmoid arg)
// [320..322] bo / 2
// [323]      fidpack (24 x 2 bits)
#define NCONST 324
__constant__ u64 cW[NCONST];
__device__ u64 g_prep[NCONST];

__device__ __forceinline__ u64 pk2(float lo, float hi) {
    u64 r; asm("mov.b64 %0, {%1, %2};" : "=l"(r) : "f"(lo), "f"(hi)); return r;
}
__device__ __forceinline__ void unpk(u64 v, float& lo, float& hi) {
    asm("mov.b64 {%0, %1}, %2;" : "=f"(lo), "=f"(hi) : "l"(v));
}
__device__ __forceinline__ u64 ffma2(u64 a, u64 b, u64 c) {
    u64 d; asm("fma.rn.f32x2 %0, %1, %2, %3;" : "=l"(d) : "l"(a), "l"(b), "l"(c)); return d;
}
__device__ __forceinline__ u64 fmul2(u64 a, u64 b) {
    u64 d; asm("mul.rn.f32x2 %0, %1, %2;" : "=l"(d) : "l"(a), "l"(b)); return d;
}
__device__ __forceinline__ float sin_ap(float x){ float r; asm("sin.approx.f32 %0, %1;" : "=f"(r) : "f"(x)); return r; }
__device__ __forceinline__ float ex2_ap(float x){ float r; asm("ex2.approx.f32 %0, %1;" : "=f"(r) : "f"(x)); return r; }
__device__ __forceinline__ float tanh_ap(float x){ float r; asm("tanh.approx.f32 %0, %1;" : "=f"(r) : "f"(x)); return r; }

// ---- prep kernel: duplicated weight pairs (with folded scales) + fid pack ----
__global__ void prep_kernel(
    const float* __restrict__ W0, const float* __restrict__ b0,
    const float* __restrict__ Wm, const float* __restrict__ bm,
    const float* __restrict__ Wo, const float* __restrict__ bo,
    const int* __restrict__ masks_raw)
{
    for (int idx = threadIdx.x; idx < 323; idx += TPB) {
        float w;
        if (idx < 88) {
            int k = idx % 11;
            w = W0[idx] * (k < 8 ? 0.1f : 1.0f);        // fold z / Z_SCALE
        } else if (idx < 96)  w = b0[idx-88];
        else if (idx < 160)   w = Wm[idx-96];            // layer 0: x1
        else if (idx < 224)   w = Wm[idx-160] * 0.5f;    // layer 1: x0.5
        else if (idx < 288)   w = Wm[idx-224] * 0.25f;   // layer 2: x0.25
        else if (idx < 296)   w = bm[idx-288];
        else if (idx < 320)   w = Wo[idx-296] * 0.0625f; // 1/8 unscale * 0.5 sig-arg
        else                  w = bo[idx-320] * 0.5f;
        g_prep[idx] = pk2(w, w);
    }
    if (threadIdx.x == 0) {
        // Parse masks: dtype may be int32 (JAX x64 off) or int64. Detect via
        // "layer 0's 8 entries must be a permutation of 0..7".
        int v[24];
        bool ok32 = true;
        unsigned m = 0;
        #pragma unroll
        for (int i = 0; i < 24; i++) v[i] = masks_raw[i];
        #pragma unroll
        for (int i = 0; i < 8; i++) {
            if ((unsigned)v[i] > 7u) ok32 = false; else m |= 1u << v[i];
        }
        if (!ok32 || m != 0xFFu) {
            const long long* m64 = (const long long*)masks_raw;
            #pragma unroll
            for (int i = 0; i < 24; i++) v[i] = (int)m64[i];
        }
        u64 pack = 0ull;
        #pragma unroll
        for (int l = 0; l < 3; l++)
            #pragma unroll
            for (int f = 0; f < 4; f++)
                #pragma unroll
                for (int i = 0; i < 2; i++) {
                    int unit = v[l*8 + f*2 + i];
                    pack |= ((u64)f) << (2 * (l*8 + unit));
                }
        g_prep[323] = pack;
    }
}

__global__ __launch_bounds__(TPB, 6) void cppn_kernel(
    const float* __restrict__ x, const float* __restrict__ y, const float* __restrict__ rr,
    const float* __restrict__ z,
    float* __restrict__ outp, long long n)
{
    const int tid = threadIdx.x;

    const u64 cgau = pk2(-0.72134752044448f, -0.72134752044448f);   // -0.5*log2(e)
    const float cisq = 0.3989422804014327f;                         // 1/sqrt(2pi)
    const u64 fidPack = cW[323];

    const unsigned p32 = (unsigned)blockIdx.x * PXB + (unsigned)tid * PXT;
    const long long p = (long long)p32;
    const bool ok = (p + PXT <= n);   // N is a multiple of 4; tail guarded whole

    // v[q] holds 2^l * out_l for pair q (pixels p+2q, p+2q+1)
    u64 v[2][8];

    { // ---- input load + first linear (W0) ----
        u64 inp[2][11];
        if (ok) {
            const float4* zp = (const float4*)(z + p * 8);
            float4 xv = *(const float4*)(x  + p);
            float4 yv = *(const float4*)(y  + p);
            float4 rv = *(const float4*)(rr + p);
            #pragma unroll
            for (int q = 0; q < 2; q++) {
                float4 a0 = zp[q*4 + 0], a1 = zp[q*4 + 1];
                float4 b0_ = zp[q*4 + 2], b1 = zp[q*4 + 3];
                inp[q][0] = pk2(a0.x, b0_.x);
                inp[q][1] = pk2(a0.y, b0_.y);
                inp[q][2] = pk2(a0.z, b0_.z);
                inp[q][3] = pk2(a0.w, b0_.w);
                inp[q][4] = pk2(a1.x, b1.x);
                inp[q][5] = pk2(a1.y, b1.y);
                inp[q][6] = pk2(a1.z, b1.z);
                inp[q][7] = pk2(a1.w, b1.w);
            }
            inp[0][8]  = pk2(xv.x, xv.y);  inp[1][8]  = pk2(xv.z, xv.w);
            inp[0][9]  = pk2(yv.x, yv.y);  inp[1][9]  = pk2(yv.z, yv.w);
            inp[0][10] = pk2(rv.x, rv.y);  inp[1][10] = pk2(rv.z, rv.w);
        } else {
            #pragma unroll
            for (int q = 0; q < 2; q++)
                #pragma unroll
                for (int k = 0; k < 11; k++) inp[q][k] = 0ull;
        }
        #pragma unroll
        for (int j = 0; j < 8; j++) {
            u64 a0 = cW[88 + j], a1 = a0;
            #pragma unroll
            for (int k = 0; k < 11; k++) {
                u64 w = cW[j*11 + k];
                a0 = ffma2(inp[0][k], w, a0);
                a1 = ffma2(inp[1][k], w, a1);
            }
            v[0][j] = a0; v[1][j] = a1;
        }
    }

    // ---- 3 residual layers on scaled accumulator ----
    #pragma unroll
    for (int l = 0; l < 3; l++) {
        const int wbase = 96 + l * 64;
        const float sclf = (l == 0) ? 1.0f : (l == 1 ? 2.0f : 4.0f);
        const u64 scl  = pk2(sclf, sclf);
        const u64 gscl = pk2(sclf * cisq, sclf * cisq);

        u64 pre[2][8];
        #pragma unroll
        for (int j = 0; j < 8; j++) {
            u64 a0 = cW[288 + j], a1 = a0;
            #pragma unroll
            for (int k = 0; k < 8; k++) {
                u64 w = cW[wbase + j*8 + k];
                a0 = ffma2(v[0][k], w, a0);
                a1 = ffma2(v[1][k], w, a1);
            }
            pre[0][j] = a0; pre[1][j] = a1;
        }
        #pragma unroll
        for (int j = 0; j < 8; j++) {
            int fid = (int)((fidPack >> (2 * (l*8 + j))) & 3ull);
            if (fid == 0) {
                #pragma unroll
                for (int q = 0; q < 2; q++) {
                    float ta, tb; unpk(pre[q][j], ta, tb);
                    v[q][j] = ffma2(pk2(sin_ap(ta), sin_ap(tb)), scl, v[q][j]);
                }
            } else if (fid == 1) {
                #pragma unroll
                for (int q = 0; q < 2; q++) {
                    u64 t = pre[q][j];
                    u64 arg = fmul2(fmul2(t, t), cgau);
                    float g0, g1; unpk(arg, g0, g1);
                    v[q][j] = ffma2(pk2(ex2_ap(g0), ex2_ap(g1)), gscl, v[q][j]);
                }
            } else if (fid == 2) {
                #pragma unroll
                for (int q = 0; q < 2; q++) {
                    float ta, tb; unpk(pre[q][j], ta, tb);
                    v[q][j] = ffma2(pk2(tanh_ap(ta), tanh_ap(tb)), scl, v[q][j]);
                }
            } else {
                #pragma unroll
                for (int q = 0; q < 2; q++)
                    v[q][j] = ffma2(pre[q][j], scl, v[q][j]);
            }
        }
    }

    // ---- output linear (Wo/16, bo/2 prefolded) + sigmoid via tanh ----
    if (ok) {
        float res[12];
        #pragma unroll
        for (int o = 0; o < 3; o++) {
            u64 a0 = cW[320 + o], a1 = a0;
            #pragma unroll
            for (int k = 0; k < 8; k++) {
                u64 w = cW[296 + o*8 + k];
                a0 = ffma2(v[0][k], w, a0);
                a1 = ffma2(v[1][k], w, a1);
            }
            float u0, u1, u2, u3;
            unpk(a0, u0, u1); unpk(a1, u2, u3);
            res[o]     = fmaf(tanh_ap(u0), 0.5f, 0.5f);
            res[3 + o] = fmaf(tanh_ap(u1), 0.5f, 0.5f);
            res[6 + o] = fmaf(tanh_ap(u2), 0.5f, 0.5f);
            res[9 + o] = fmaf(tanh_ap(u3), 0.5f, 0.5f);
        }
        float4* op = (float4*)(outp + p * 3);   // p % 4 == 0 -> 16B aligned
        op[0] = make_float4(res[0], res[1], res[2],  res[3]);
        op[1] = make_float4(res[4], res[5], res[6],  res[7]);
        op[2] = make_float4(res[8], res[9], res[10], res[11]);
    }
}

extern "C" void kernel_launch(void* const* d_in, const int* in_sizes, int n_in,
                              void* d_out, int out_size) {
    const float* x  = (const float*)d_in[0];
    const float* y  = (const float*)d_in[1];
    const float* r  = (const float*)d_in[2];
    const float* z  = (const float*)d_in[3];
    const float* W0 = (const float*)d_in[4];
    const float* b0 = (const float*)d_in[5];
    const float* Wm = (const float*)d_in[6];
    const float* bm = (const float*)d_in[7];
    const float* Wo = (const float*)d_in[8];
    const float* bo = (const float*)d_in[9];
    const int* masks = (const int*)d_in[10];

    long long n = (long long)in_sizes[0];

    prep_kernel<<<1, TPB>>>(W0, b0, Wm, bm, Wo, bo, masks);

    // Resolve the REAL device address of g_prep (symbol name in host code is
    // only a shadow) and copy into the constant bank as a graph memcpy node.
    void* src = 0;
    cudaGetSymbolAddress(&src, g_prep);
    cudaMemcpyToSymbolAsync(cW, src, NCONST * sizeof(u64), 0,
                            cudaMemcpyDeviceToDevice, 0);

    int blocks = (int)((n + PXB - 1) / PXB);
    cppn_kernel<<<blocks, TPB>>>(x, y, r, z, (float*)d_out, n);
}

// round 12
// speedup vs baseline: 1.0038x; 1.0038x over previous
#include <cuda_runtime.h>

typedef unsigned long long u64;

#define TPB 128
#define PXT 4                    // pixels per thread (2 f32x2 pairs)
#define PXB (TPB * PXT)          // 512 pixels per block

// constant layout (u64 duplicated pairs):
// [0..87]    W0 (8x11, z-scale folded)
// [88..95]   b0
// [96..159]  Wm * 1      (layer 0)
// [160..223] Wm * 0.5    (layer 1)
// [224..287] Wm * 0.25   (layer 2)
// [288..295] bm
// [296..319] Wo / 16     (1/8 residual unscale + 0.5 sigmoid arg)
// [320..322] bo / 2
// [323]      fidpack (24 x 2 bits)
#define NCONST 324
__constant__ u64 cW[NCONST];
__device__ u64 g_prep[NCONST];

__device__ __forceinline__ u64 pk2(float lo, float hi) {
    u64 r; asm("mov.b64 %0, {%1, %2};" : "=l"(r) : "f"(lo), "f"(hi)); return r;
}
__device__ __forceinline__ void unpk(u64 v, float& lo, float& hi) {
    asm("mov.b64 {%0, %1}, %2;" : "=f"(lo), "=f"(hi) : "l"(v));
}
__device__ __forceinline__ u64 ffma2(u64 a, u64 b, u64 c) {
    u64 d; asm("fma.rn.f32x2 %0, %1, %2, %3;" : "=l"(d) : "l"(a), "l"(b), "l"(c)); return d;
}
__device__ __forceinline__ u64 fmul2(u64 a, u64 b) {
    u64 d; asm("mul.rn.f32x2 %0, %1, %2;" : "=l"(d) : "l"(a), "l"(b)); return d;
}
__device__ __forceinline__ float sin_ap(float x){ float r; asm("sin.approx.f32 %0, %1;" : "=f"(r) : "f"(x)); return r; }
__device__ __forceinline__ float ex2_ap(float x){ float r; asm("ex2.approx.f32 %0, %1;" : "=f"(r) : "f"(x)); return r; }
__device__ __forceinline__ float tanh_ap(float x){ float r; asm("tanh.approx.f32 %0, %1;" : "=f"(r) : "f"(x)); return r; }

// ---- prep kernel: duplicated weight pairs (with folded scales) + fid pack ----
__global__ void prep_kernel(
    const float* __restrict__ W0, const float* __restrict__ b0,
    const float* __restrict__ Wm, const float* __restrict__ bm,
    const float* __restrict__ Wo, const float* __restrict__ bo,
    const int* __restrict__ masks_raw)
{
    for (int idx = threadIdx.x; idx < 323; idx += TPB) {
        float w;
        if (idx < 88) {
            int k = idx % 11;
            w = W0[idx] * (k < 8 ? 0.1f : 1.0f);        // fold z / Z_SCALE
        } else if (idx < 96)  w = b0[idx-88];
        else if (idx < 160)   w = Wm[idx-96];            // layer 0: x1
        else if (idx < 224)   w = Wm[idx-160] * 0.5f;    // layer 1: x0.5
        else if (idx < 288)   w = Wm[idx-224] * 0.25f;   // layer 2: x0.25
        else if (idx < 296)   w = bm[idx-288];
        else if (idx < 320)   w = Wo[idx-296] * 0.0625f; // 1/8 unscale * 0.5 sig-arg
        else                  w = bo[idx-320] * 0.5f;
        g_prep[idx] = pk2(w, w);
    }
    if (threadIdx.x == 0) {
        // Parse masks: dtype may be int32 (JAX x64 off) or int64. Detect via
        // "layer 0's 8 entries must be a permutation of 0..7".
        int v[24];
        bool ok32 = true;
        unsigned m = 0;
        #pragma unroll
        for (int i = 0; i < 24; i++) v[i] = masks_raw[i];
        #pragma unroll
        for (int i = 0; i < 8; i++) {
            if ((unsigned)v[i] > 7u) ok32 = false; else m |= 1u << v[i];
        }
        if (!ok32 || m != 0xFFu) {
            const long long* m64 = (const long long*)masks_raw;
            #pragma unroll
            for (int i = 0; i < 24; i++) v[i] = (int)m64[i];
        }
        u64 pack = 0ull;
        #pragma unroll
        for (int l = 0; l < 3; l++)
            #pragma unroll
            for (int f = 0; f < 4; f++)
                #pragma unroll
                for (int i = 0; i < 2; i++) {
                    int unit = v[l*8 + f*2 + i];
                    pack |= ((u64)f) << (2 * (l*8 + unit));
                }
        g_prep[323] = pack;
    }
}

__global__ __launch_bounds__(TPB, 6) void cppn_kernel(
    const float* __restrict__ x, const float* __restrict__ y, const float* __restrict__ rr,
    const float* __restrict__ z,
    float* __restrict__ outp, long long n)
{
    const int tid = threadIdx.x;

    const u64 cgau = pk2(-0.72134752044448f, -0.72134752044448f);   // -0.5*log2(e)
    const float cisq = 0.3989422804014327f;                         // 1/sqrt(2pi)
    const u64 fidPack = cW[323];

    const unsigned p32 = (unsigned)blockIdx.x * PXB + (unsigned)tid * PXT;
    const long long p = (long long)p32;
    const bool ok = (p + PXT <= n);   // N is a multiple of 4; tail guarded whole

    // v[q] holds 2^l * out_l for pair q (pixels p+2q, p+2q+1)
    u64 v[2][8];

    { // ---- input load + first linear (W0) ----
        u64 inp[2][11];
        if (ok) {
            const float4* zp = (const float4*)(z + p * 8);
            float4 xv = *(const float4*)(x  + p);
            float4 yv = *(const float4*)(y  + p);
            float4 rv = *(const float4*)(rr + p);
            #pragma unroll
            for (int q = 0; q < 2; q++) {
                float4 a0 = zp[q*4 + 0], a1 = zp[q*4 + 1];
                float4 b0_ = zp[q*4 + 2], b1 = zp[q*4 + 3];
                inp[q][0] = pk2(a0.x, b0_.x);
                inp[q][1] = pk2(a0.y, b0_.y);
                inp[q][2] = pk2(a0.z, b0_.z);
                inp[q][3] = pk2(a0.w, b0_.w);
                inp[q][4] = pk2(a1.x, b1.x);
                inp[q][5] = pk2(a1.y, b1.y);
                inp[q][6] = pk2(a1.z, b1.z);
                inp[q][7] = pk2(a1.w, b1.w);
            }
            inp[0][8]  = pk2(xv.x, xv.y);  inp[1][8]  = pk2(xv.z, xv.w);
            inp[0][9]  = pk2(yv.x, yv.y);  inp[1][9]  = pk2(yv.z, yv.w);
            inp[0][10] = pk2(rv.x, rv.y);  inp[1][10] = pk2(rv.z, rv.w);
        } else {
            #pragma unroll
            for (int q = 0; q < 2; q++)
                #pragma unroll
                for (int k = 0; k < 11; k++) inp[q][k] = 0ull;
        }
        #pragma unroll
        for (int j = 0; j < 8; j++) {
            u64 a0 = cW[88 + j], a1 = a0;
            #pragma unroll
            for (int k = 0; k < 11; k++) {
                u64 w = cW[j*11 + k];
                a0 = ffma2(inp[0][k], w, a0);
                a1 = ffma2(inp[1][k], w, a1);
            }
            v[0][j] = a0; v[1][j] = a1;
        }
    }

    // ---- 3 residual layers on scaled accumulator ----
    #pragma unroll
    for (int l = 0; l < 3; l++) {
        const int wbase = 96 + l * 64;
        const float sclf = (l == 0) ? 1.0f : (l == 1 ? 2.0f : 4.0f);
        const u64 scl  = pk2(sclf, sclf);
        const u64 gscl = pk2(sclf * cisq, sclf * cisq);

        u64 pre[2][8];
        #pragma unroll
        for (int j = 0; j < 8; j++) {
            u64 a0 = cW[288 + j], a1 = a0;
            #pragma unroll
            for (int k = 0; k < 8; k++) {
                u64 w = cW[wbase + j*8 + k];
                a0 = ffma2(v[0][k], w, a0);
                a1 = ffma2(v[1][k], w, a1);
            }
            pre[0][j] = a0; pre[1][j] = a1;
        }
        #pragma unroll
        for (int j = 0; j < 8; j++) {
            int fid = (int)((fidPack >> (2 * (l*8 + j))) & 3ull);
            if (fid == 0) {
                #pragma unroll
                for (int q = 0; q < 2; q++) {
                    float ta, tb; unpk(pre[q][j], ta, tb);
                    v[q][j] = ffma2(pk2(sin_ap(ta), sin_ap(tb)), scl, v[q][j]);
                }
            } else if (fid == 1) {
                #pragma unroll
                for (int q = 0; q < 2; q++) {
                    u64 t = pre[q][j];
                    u64 arg = fmul2(fmul2(t, t), cgau);
                    float g0, g1; unpk(arg, g0, g1);
                    v[q][j] = ffma2(pk2(ex2_ap(g0), ex2_ap(g1)), gscl, v[q][j]);
                }
            } else if (fid == 2) {
                #pragma unroll
                for (int q = 0; q < 2; q++) {
                    float ta, tb; unpk(pre[q][j], ta, tb);
                    v[q][j] = ffma2(pk2(tanh_ap(ta), tanh_ap(tb)), scl, v[q][j]);
                }
            } else {
                #pragma unroll
                for (int q = 0; q < 2; q++)
                    v[q][j] = ffma2(pre[q][j], scl, v[q][j]);
            }
        }
    }

    // ---- output linear (Wo/16, bo/2 prefolded) + sigmoid via tanh ----
    if (ok) {
        float res[12];
        #pragma unroll
        for (int o = 0; o < 3; o++) {
            u64 a0 = cW[320 + o], a1 = a0;
            #pragma unroll
            for (int k = 0; k < 8; k++) {
                u64 w = cW[296 + o*8 + k];
                a0 = ffma2(v[0][k], w, a0);
                a1 = ffma2(v[1][k], w, a1);
            }
            float u0, u1, u2, u3;
            unpk(a0, u0, u1); unpk(a1, u2, u3);
            res[o]     = fmaf(tanh_ap(u0), 0.5f, 0.5f);
            res[3 + o] = fmaf(tanh_ap(u1), 0.5f, 0.5f);
            res[6 + o] = fmaf(tanh_ap(u2), 0.5f, 0.5f);
            res[9 + o] = fmaf(tanh_ap(u3), 0.5f, 0.5f);
        }
        float4* op = (float4*)(outp + p * 3);   // p % 4 == 0 -> 16B aligned
        op[0] = make_float4(res[0], res[1], res[2],  res[3]);
        op[1] = make_float4(res[4], res[5], res[6],  res[7]);
        op[2] = make_float4(res[8], res[9], res[10], res[11]);
    }
}

extern "C" void kernel_launch(void* const* d_in, const int* in_sizes, int n_in,
                              void* d_out, int out_size) {
    const float* x  = (const float*)d_in[0];
    const float* y  = (const float*)d_in[1];
    const float* r  = (const float*)d_in[2];
    const float* z  = (const float*)d_in[3];
    const float* W0 = (const float*)d_in[4];
    const float* b0 = (const float*)d_in[5];
    const float* Wm = (const float*)d_in[6];
    const float* bm = (const float*)d_in[7];
    const float* Wo = (const float*)d_in[8];
    const float* bo = (const float*)d_in[9];
    const int* masks = (const int*)d_in[10];

    long long n = (long long)in_sizes[0];

    prep_kernel<<<1, TPB>>>(W0, b0, Wm, bm, Wo, bo, masks);

    // Resolve the REAL device address of g_prep (symbol name in host code is
    // only a shadow) and copy into the constant bank as a graph memcpy node.
    void* src = 0;
    cudaGetSymbolAddress(&src, g_prep);
    cudaMemcpyToSymbolAsync(cW, src, NCONST * sizeof(u64), 0,
                            cudaMemcpyDeviceToDevice, 0);

    int blocks = (int)((n + PXB - 1) / PXB);
    cppn_kernel<<<blocks, TPB>>>(x, y, r, z, (float*)d_out, n);
}

// round 13
// speedup vs baseline: 1.0339x; 1.0300x over previous
#include <cuda_runtime.h>

typedef unsigned long long u64;

#define TPB 128
#define PXT 4                    // pixels per thread (2 f32x2 pairs)
#define PXB (TPB * PXT)          // 512 pixels per block

// constant layout (u64 duplicated pairs):
// [0..87]    W0 (8x11, z-scale folded)
// [88..95]   b0
// [96..159]  Wm * 1      (layer 0)
// [160..223] Wm * 0.5    (layer 1)
// [224..287] Wm * 0.25   (layer 2)
// [288..295] bm
// [296..319] Wo / 16     (1/8 residual unscale + 0.5 sigmoid arg)
// [320..322] bo / 2
// [323]      fidpack (24 x 2 bits)
#define NCONST 324
__constant__ u64 cW[NCONST];
__device__ u64 g_prep[NCONST];

__device__ __forceinline__ u64 pk2(float lo, float hi) {
    u64 r; asm("mov.b64 %0, {%1, %2};" : "=l"(r) : "f"(lo), "f"(hi)); return r;
}
__device__ __forceinline__ void unpk(u64 v, float& lo, float& hi) {
    asm("mov.b64 {%0, %1}, %2;" : "=f"(lo), "=f"(hi) : "l"(v));
}
__device__ __forceinline__ u64 ffma2(u64 a, u64 b, u64 c) {
    u64 d; asm("fma.rn.f32x2 %0, %1, %2, %3;" : "=l"(d) : "l"(a), "l"(b), "l"(c)); return d;
}
__device__ __forceinline__ u64 fmul2(u64 a, u64 b) {
    u64 d; asm("mul.rn.f32x2 %0, %1, %2;" : "=l"(d) : "l"(a), "l"(b)); return d;
}
__device__ __forceinline__ float sin_ap(float x){ float r; asm("sin.approx.f32 %0, %1;" : "=f"(r) : "f"(x)); return r; }
__device__ __forceinline__ float ex2_ap(float x){ float r; asm("ex2.approx.f32 %0, %1;" : "=f"(r) : "f"(x)); return r; }
__device__ __forceinline__ float tanh_ap(float x){ float r; asm("tanh.approx.f32 %0, %1;" : "=f"(r) : "f"(x)); return r; }

// ---- prep kernel: duplicated weight pairs (with folded scales) + fid pack ----
__global__ void prep_kernel(
    const float* __restrict__ W0, const float* __restrict__ b0,
    const float* __restrict__ Wm, const float* __restrict__ bm,
    const float* __restrict__ Wo, const float* __restrict__ bo,
    const int* __restrict__ masks_raw)
{
    for (int idx = threadIdx.x; idx < 323; idx += TPB) {
        float w;
        if (idx < 88) {
            int k = idx % 11;
            w = W0[idx] * (k < 8 ? 0.1f : 1.0f);        // fold z / Z_SCALE
        } else if (idx < 96)  w = b0[idx-88];
        else if (idx < 160)   w = Wm[idx-96];            // layer 0: x1
        else if (idx < 224)   w = Wm[idx-160] * 0.5f;    // layer 1: x0.5
        else if (idx < 288)   w = Wm[idx-224] * 0.25f;   // layer 2: x0.25
        else if (idx < 296)   w = bm[idx-288];
        else if (idx < 320)   w = Wo[idx-296] * 0.0625f; // 1/8 unscale * 0.5 sig-arg
        else                  w = bo[idx-320] * 0.5f;
        g_prep[idx] = pk2(w, w);
    }
    if (threadIdx.x == 0) {
        // Parse masks: dtype may be int32 (JAX x64 off) or int64. Detect via
        // "layer 0's 8 entries must be a permutation of 0..7".
        int v[24];
        bool ok32 = true;
        unsigned m = 0;
        #pragma unroll
        for (int i = 0; i < 24; i++) v[i] = masks_raw[i];
        #pragma unroll
        for (int i = 0; i < 8; i++) {
            if ((unsigned)v[i] > 7u) ok32 = false; else m |= 1u << v[i];
        }
        if (!ok32 || m != 0xFFu) {
            const long long* m64 = (const long long*)masks_raw;
            #pragma unroll
            for (int i = 0; i < 24; i++) v[i] = (int)m64[i];
        }
        u64 pack = 0ull;
        #pragma unroll
        for (int l = 0; l < 3; l++)
            #pragma unroll
            for (int f = 0; f < 4; f++)
                #pragma unroll
                for (int i = 0; i < 2; i++) {
                    int unit = v[l*8 + f*2 + i];
                    pack |= ((u64)f) << (2 * (l*8 + unit));
                }
        g_prep[323] = pack;
    }
}

__global__ __launch_bounds__(TPB, 7) void cppn_kernel(
    const float* __restrict__ x, const float* __restrict__ y, const float* __restrict__ rr,
    const float* __restrict__ z,
    float* __restrict__ outp, long long n)
{
    const int tid = threadIdx.x;

    const u64 cgau = pk2(-0.72134752044448f, -0.72134752044448f);   // -0.5*log2(e)
    const float cisq = 0.3989422804014327f;                         // 1/sqrt(2pi)
    const u64 fidPack = cW[323];

    const unsigned p32 = (unsigned)blockIdx.x * PXB + (unsigned)tid * PXT;
    const long long p = (long long)p32;
    const bool ok = (p + PXT <= n);   // N is a multiple of 4; tail guarded whole

    // v[q] holds 2^l * out_l for pair q (pixels p+2q, p+2q+1)
    u64 v[2][8];

    // ---- input load + first linear (W0), ONE PAIR AT A TIME to cut peak regs ----
    #pragma unroll
    for (int q = 0; q < 2; q++) {
        u64 inp[11];
        if (ok) {
            const long long pq = p + 2*q;
            const float4* zp = (const float4*)(z + pq * 8);
            float4 a0 = zp[0], a1 = zp[1], b0_ = zp[2], b1 = zp[3];
            float2 xv = *(const float2*)(x  + pq);
            float2 yv = *(const float2*)(y  + pq);
            float2 rv = *(const float2*)(rr + pq);
            inp[0]  = pk2(a0.x, b0_.x);
            inp[1]  = pk2(a0.y, b0_.y);
            inp[2]  = pk2(a0.z, b0_.z);
            inp[3]  = pk2(a0.w, b0_.w);
            inp[4]  = pk2(a1.x, b1.x);
            inp[5]  = pk2(a1.y, b1.y);
            inp[6]  = pk2(a1.z, b1.z);
            inp[7]  = pk2(a1.w, b1.w);
            inp[8]  = pk2(xv.x, xv.y);
            inp[9]  = pk2(yv.x, yv.y);
            inp[10] = pk2(rv.x, rv.y);
        } else {
            #pragma unroll
            for (int k = 0; k < 11; k++) inp[k] = 0ull;
        }
        #pragma unroll
        for (int j = 0; j < 8; j++) {
            u64 a = cW[88 + j];
            #pragma unroll
            for (int k = 0; k < 11; k++) a = ffma2(inp[k], cW[j*11 + k], a);
            v[q][j] = a;
        }
    }

    // ---- 3 residual layers on scaled accumulator ----
    #pragma unroll
    for (int l = 0; l < 3; l++) {
        const int wbase = 96 + l * 64;
        const float sclf = (l == 0) ? 1.0f : (l == 1 ? 2.0f : 4.0f);
        const u64 scl  = pk2(sclf, sclf);
        const u64 gscl = pk2(sclf * cisq, sclf * cisq);

        u64 pre[2][8];
        #pragma unroll
        for (int j = 0; j < 8; j++) {
            u64 a0 = cW[288 + j], a1 = a0;
            #pragma unroll
            for (int k = 0; k < 8; k++) {
                u64 w = cW[wbase + j*8 + k];
                a0 = ffma2(v[0][k], w, a0);
                a1 = ffma2(v[1][k], w, a1);
            }
            pre[0][j] = a0; pre[1][j] = a1;
        }
        #pragma unroll
        for (int j = 0; j < 8; j++) {
            int fid = (int)((fidPack >> (2 * (l*8 + j))) & 3ull);
            if (fid == 0) {
                #pragma unroll
                for (int q = 0; q < 2; q++) {
                    float ta, tb; unpk(pre[q][j], ta, tb);
                    v[q][j] = ffma2(pk2(sin_ap(ta), sin_ap(tb)), scl, v[q][j]);
                }
            } else if (fid == 1) {
                #pragma unroll
                for (int q = 0; q < 2; q++) {
                    u64 t = pre[q][j];
                    u64 arg = fmul2(fmul2(t, t), cgau);
                    float g0, g1; unpk(arg, g0, g1);
                    v[q][j] = ffma2(pk2(ex2_ap(g0), ex2_ap(g1)), gscl, v[q][j]);
                }
            } else if (fid == 2) {
                #pragma unroll
                for (int q = 0; q < 2; q++) {
                    float ta, tb; unpk(pre[q][j], ta, tb);
                    v[q][j] = ffma2(pk2(tanh_ap(ta), tanh_ap(tb)), scl, v[q][j]);
                }
            } else {
                #pragma unroll
                for (int q = 0; q < 2; q++)
                    v[q][j] = ffma2(pre[q][j], scl, v[q][j]);
            }
        }
    }

    // ---- output linear (Wo/16, bo/2 prefolded) + sigmoid via tanh ----
    if (ok) {
        float res[12];
        #pragma unroll
        for (int o = 0; o < 3; o++) {
            u64 a0 = cW[320 + o], a1 = a0;
            #pragma unroll
            for (int k = 0; k < 8; k++) {
                u64 w = cW[296 + o*8 + k];
                a0 = ffma2(v[0][k], w, a0);
                a1 = ffma2(v[1][k], w, a1);
            }
            float u0, u1, u2, u3;
            unpk(a0, u0, u1); unpk(a1, u2, u3);
            res[o]     = fmaf(tanh_ap(u0), 0.5f, 0.5f);
            res[3 + o] = fmaf(tanh_ap(u1), 0.5f, 0.5f);
            res[6 + o] = fmaf(tanh_ap(u2), 0.5f, 0.5f);
            res[9 + o] = fmaf(tanh_ap(u3), 0.5f, 0.5f);
        }
        float4* op = (float4*)(outp + p * 3);   // p % 4 == 0 -> 16B aligned
        op[0] = make_float4(res[0], res[1], res[2],  res[3]);
        op[1] = make_float4(res[4], res[5], res[6],  res[7]);
        op[2] = make_float4(res[8], res[9], res[10], res[11]);
    }
}

extern "C" void kernel_launch(void* const* d_in, const int* in_sizes, int n_in,
                              void* d_out, int out_size) {
    const float* x  = (const float*)d_in[0];
    const float* y  = (const float*)d_in[1];
    const float* r  = (const float*)d_in[2];
    const float* z  = (const float*)d_in[3];
    const float* W0 = (const float*)d_in[4];
    const float* b0 = (const float*)d_in[5];
    const float* Wm = (const float*)d_in[6];
    const float* bm = (const float*)d_in[7];
    const float* Wo = (const float*)d_in[8];
    const float* bo = (const float*)d_in[9];
    const int* masks = (const int*)d_in[10];

    long long n = (long long)in_sizes[0];

    prep_kernel<<<1, TPB>>>(W0, b0, Wm, bm, Wo, bo, masks);

    // Resolve the REAL device address of g_prep (symbol name in host code is
    // only a shadow) and copy into the constant bank as a graph memcpy node.
    void* src = 0;
    cudaGetSymbolAddress(&src, g_prep);
    cudaMemcpyToSymbolAsync(cW, src, NCONST * sizeof(u64), 0,
                            cudaMemcpyDeviceToDevice, 0);

    int blocks = (int)((n + PXB - 1) / PXB);
    cppn_kernel<<<blocks, TPB>>>(x, y, r, z, (float*)d_out, n);
}